// round 12
// baseline (speedup 1.0000x reference)
#include <cuda_runtime.h>
#include <cuda_bf16.h>
#include <cstdint>

#define NNODES 50000
#define NEDGES 800000
#define DIM 128
#define SCAN_BLOCKS ((NNODES + 255) / 256)   // 196

// ---------------- scratch (static __device__, no allocs) ----------------
__device__ float g_z[NNODES * DIM];
__device__ float g_x[NNODES * DIM];
__device__ float g_ssrc[NNODES];
__device__ float g_sdst[NNODES];
__device__ int   g_deg[NNODES];
__device__ int   g_off[NNODES + 1];
__device__ int   g_cur[NNODES];
__device__ int   g_csr_src[NEDGES];
__device__ int   g_bsum[SCAN_BLOCKS];
__device__ int   g_bbase[SCAN_BLOCKS];
__device__ float g_hg[DIM];
__device__ int   g_tick;
__device__ int   g_flag;

// ---------------- CSR build ----------------
__global__ void hist_kernel(const int* __restrict__ dst) {
    int q = blockIdx.x * blockDim.x + threadIdx.x;
    if (q == 0) { g_tick = 0; g_flag = 0; }
    if (q * 4 < NEDGES) {
        int4 d4 = ((const int4*)dst)[q];
        atomicAdd(&g_deg[d4.x], 1);
        atomicAdd(&g_deg[d4.y], 1);
        atomicAdd(&g_deg[d4.z], 1);
        atomicAdd(&g_deg[d4.w], 1);
    }
}

// single-kernel scan (one wave, 196 blocks); also zeros g_hg
__global__ void scan_fused_kernel() {
    __shared__ int sh[256];
    __shared__ int last;
    int t = threadIdx.x;
    int b = blockIdx.x;
    int i = b * 256 + t;
    if (b == 0 && t < DIM) g_hg[t] = 0.f;
    int v = (i < NNODES) ? g_deg[i] : 0;
    sh[t] = v;
    __syncthreads();
    for (int o = 1; o < 256; o <<= 1) {
        int u = (t >= o) ? sh[t - o] : 0;
        __syncthreads();
        sh[t] += u;
        __syncthreads();
    }
    int incl = sh[t];
    if (t == 255) g_bsum[b] = incl;
    __threadfence();
    if (t == 0) {
        int x = atomicAdd(&g_tick, 1);
        last = (x == gridDim.x - 1) ? 1 : 0;
    }
    __syncthreads();
    if (last) {
        __shared__ int sh2[256];
        sh2[t] = (t < SCAN_BLOCKS) ? g_bsum[t] : 0;
        __syncthreads();
        for (int o = 1; o < 256; o <<= 1) {
            int u = (t >= o) ? sh2[t - o] : 0;
            __syncthreads();
            sh2[t] += u;
            __syncthreads();
        }
        if (t < SCAN_BLOCKS) g_bbase[t] = (t == 0) ? 0 : sh2[t - 1];
        if (t == 0) g_off[NNODES] = sh2[SCAN_BLOCKS - 1];
        __threadfence();
        __syncthreads();
        if (t == 0) atomicExch(&g_flag, 1);
    } else {
        if (t == 0) {
            while (atomicAdd(&g_flag, 0) == 0) { }
        }
        __syncthreads();
    }
    if (i < NNODES) {
        int excl = g_bbase[b] + incl - v;
        g_off[i] = excl;
        g_cur[i] = excl;
    }
}

__global__ void scatter_kernel(const int* __restrict__ src, const int* __restrict__ dst) {
    int q = blockIdx.x * blockDim.x + threadIdx.x;
    if (q * 4 < NEDGES) {
        int4 d4 = ((const int4*)dst)[q];
        int4 s4 = ((const int4*)src)[q];
        int p0 = atomicAdd(&g_cur[d4.x], 1);
        int p1 = atomicAdd(&g_cur[d4.y], 1);
        int p2 = atomicAdd(&g_cur[d4.z], 1);
        int p3 = atomicAdd(&g_cur[d4.w], 1);
        g_csr_src[p0] = s4.x;
        g_csr_src[p1] = s4.y;
        g_csr_src[p2] = s4.z;
        g_csr_src[p3] = s4.w;
    }
}

// ---------------- TF32 tensor-core GEMM + fused attention scores ----------------
// 512 threads = 16 warps; warp tile 16x64.
#define BM 128
#define BK 32
#define ASTRIDE 40
#define BSTRIDE 136

__device__ __forceinline__ uint32_t f2tf32(float f) {
    uint32_t u;
    asm("cvt.rna.tf32.f32 %0, %1;" : "=r"(u) : "f"(f));
    return u;
}

__device__ __forceinline__ void mma_tf32(float* d, uint32_t a0, uint32_t a1, uint32_t a2,
                                         uint32_t a3, uint32_t b0, uint32_t b1) {
    asm volatile(
        "mma.sync.aligned.m16n8k8.row.col.f32.tf32.tf32.f32 "
        "{%0,%1,%2,%3}, {%4,%5,%6,%7}, {%8,%9}, {%0,%1,%2,%3};\n"
        : "+f"(d[0]), "+f"(d[1]), "+f"(d[2]), "+f"(d[3])
        : "r"(a0), "r"(a1), "r"(a2), "r"(a3), "r"(b0), "r"(b1));
}

__global__ void __launch_bounds__(512) gemm_score_kernel(const float* __restrict__ A,
                                                         const float* __restrict__ W,
                                                         const float* __restrict__ att,
                                                         float* __restrict__ Z, int M) {
    __shared__ uint32_t As[BM * ASTRIDE];
    __shared__ uint32_t Bs[BK * BSTRIDE];
    __shared__ float sS1[2][BM];
    __shared__ float sS2[2][BM];
    const int tid = threadIdx.x;
    const int warp = tid >> 5;
    const int lane = tid & 31;
    const int gid = lane >> 2;
    const int tig = lane & 3;
    const int wr = warp >> 1;
    const int wc = warp & 1;
    const int brow = blockIdx.x * BM;

    const int ar[2] = {(tid + 0) >> 3, (tid + 512) >> 3};
    const int ac = (tid & 7) * 4;
    const int br[2] = {(tid + 0) >> 5, (tid + 512) >> 5};
    const int bc = (tid & 31) * 4;

    float acc[8][4];
#pragma unroll
    for (int i = 0; i < 8; i++)
#pragma unroll
        for (int j = 0; j < 4; j++) acc[i][j] = 0.f;

    float4 pa[2], pb[2];
#pragma unroll
    for (int i = 0; i < 2; i++) {
        pa[i] = make_float4(0.f, 0.f, 0.f, 0.f);
        if (brow + ar[i] < M) pa[i] = *(const float4*)&A[(brow + ar[i]) * 128 + 0 + ac];
        pb[i] = *(const float4*)&W[br[i] * 128 + bc];
    }

#pragma unroll
    for (int t = 0; t < 4; t++) {
#pragma unroll
        for (int i = 0; i < 2; i++) {
            uint32_t* p = &As[ar[i] * ASTRIDE + ac];
            p[0] = f2tf32(pa[i].x); p[1] = f2tf32(pa[i].y);
            p[2] = f2tf32(pa[i].z); p[3] = f2tf32(pa[i].w);
            uint32_t* q = &Bs[br[i] * BSTRIDE + bc];
            q[0] = f2tf32(pb[i].x); q[1] = f2tf32(pb[i].y);
            q[2] = f2tf32(pb[i].z); q[3] = f2tf32(pb[i].w);
        }
        __syncthreads();
        if (t < 3) {
            int k0 = (t + 1) * BK;
#pragma unroll
            for (int i = 0; i < 2; i++) {
                pa[i] = make_float4(0.f, 0.f, 0.f, 0.f);
                if (brow + ar[i] < M) pa[i] = *(const float4*)&A[(brow + ar[i]) * 128 + k0 + ac];
                pb[i] = *(const float4*)&W[(k0 + br[i]) * 128 + bc];
            }
        }
#pragma unroll
        for (int kk = 0; kk < 4; kk++) {
            const int wrow = wr * 16;
            uint32_t a0 = As[(wrow + gid) * ASTRIDE + kk * 8 + tig];
            uint32_t a1 = As[(wrow + gid + 8) * ASTRIDE + kk * 8 + tig];
            uint32_t a2 = As[(wrow + gid) * ASTRIDE + kk * 8 + tig + 4];
            uint32_t a3 = As[(wrow + gid + 8) * ASTRIDE + kk * 8 + tig + 4];
#pragma unroll
            for (int nt = 0; nt < 8; nt++) {
                const int n = wc * 64 + nt * 8 + gid;
                uint32_t b0 = Bs[(kk * 8 + tig) * BSTRIDE + n];
                uint32_t b1 = Bs[(kk * 8 + tig + 4) * BSTRIDE + n];
                mma_tf32(acc[nt], a0, a1, a2, a3, b0, b1);
            }
        }
        __syncthreads();
    }

    const int r0 = brow + wr * 16 + gid;
    const int r1 = r0 + 8;
    float s1a = 0.f, s2a = 0.f, s1b = 0.f, s2b = 0.f;
#pragma unroll
    for (int nt = 0; nt < 8; nt++) {
        int col = wc * 64 + nt * 8 + tig * 2;
        float al0 = __ldg(&att[col]);
        float al1 = __ldg(&att[col + 1]);
        float ah0 = __ldg(&att[128 + col]);
        float ah1 = __ldg(&att[128 + col + 1]);
        if (r0 < M) *(float2*)&Z[r0 * 128 + col] = make_float2(acc[nt][0], acc[nt][1]);
        if (r1 < M) *(float2*)&Z[r1 * 128 + col] = make_float2(acc[nt][2], acc[nt][3]);
        s1a += acc[nt][0] * al0 + acc[nt][1] * al1;
        s2a += acc[nt][0] * ah0 + acc[nt][1] * ah1;
        s1b += acc[nt][2] * al0 + acc[nt][3] * al1;
        s2b += acc[nt][2] * ah0 + acc[nt][3] * ah1;
    }
#pragma unroll
    for (int o = 1; o <= 2; o <<= 1) {
        s1a += __shfl_xor_sync(0xffffffffu, s1a, o);
        s2a += __shfl_xor_sync(0xffffffffu, s2a, o);
        s1b += __shfl_xor_sync(0xffffffffu, s1b, o);
        s2b += __shfl_xor_sync(0xffffffffu, s2b, o);
    }
    if (tig == 0) {
        sS1[wc][wr * 16 + gid] = s1a;
        sS2[wc][wr * 16 + gid] = s2a;
        sS1[wc][wr * 16 + gid + 8] = s1b;
        sS2[wc][wr * 16 + gid + 8] = s2b;
    }
    __syncthreads();
    if (tid < BM) {
        int r = brow + tid;
        if (r < M) {
            g_ssrc[r] = sS1[0][tid] + sS1[1][tid];
            g_sdst[r] = sS2[0][tid] + sS2[1][tid];
        }
    }
}

// ---------------- fused softmax + aggregation (one warp per dst node) --------
// deg<=32 path: ILP-8 batched z-row gathers (8 loads in flight before FMAs).
#define ACC4(A, W4, Z4) \
    A.x += W4 * Z4.x; A.y += W4 * Z4.y; A.z += W4 * Z4.z; A.w += W4 * Z4.w;

__global__ void agg_kernel(int do_elu) {
    int gw = (blockIdx.x * blockDim.x + threadIdx.x) >> 5;
    int lane = threadIdx.x & 31;
    if (gw >= NNODES) return;
    const int beg = g_off[gw];
    const int end = g_off[gw + 1];
    const int deg = end - beg;
    const float4* zrows = (const float4*)g_z;

    float4 o4 = make_float4(0.f, 0.f, 0.f, 0.f);
    if (deg > 0 && deg <= 32) {
        int sidx = 0;
        float w = 0.f;
        if (lane < deg) {
            sidx = __ldg(&g_csr_src[beg + lane]);
            float e = __ldg(&g_ssrc[sidx]) + g_sdst[gw];
            e = (e > 0.f) ? e : 0.01f * e;
            w = __expf(e);
        }
        float d = w;
#pragma unroll
        for (int o = 16; o > 0; o >>= 1) d += __shfl_xor_sync(0xffffffffu, d, o);

        float4 acc0 = make_float4(0.f, 0.f, 0.f, 0.f);
        float4 acc1 = make_float4(0.f, 0.f, 0.f, 0.f);
        float4 acc2 = make_float4(0.f, 0.f, 0.f, 0.f);
        float4 acc3 = make_float4(0.f, 0.f, 0.f, 0.f);
        float4 acc4 = make_float4(0.f, 0.f, 0.f, 0.f);
        float4 acc5 = make_float4(0.f, 0.f, 0.f, 0.f);
        float4 acc6 = make_float4(0.f, 0.f, 0.f, 0.f);
        float4 acc7 = make_float4(0.f, 0.f, 0.f, 0.f);
        int j = 0;
        for (; j + 8 <= deg; j += 8) {
            int s0 = __shfl_sync(0xffffffffu, sidx, j);
            int s1 = __shfl_sync(0xffffffffu, sidx, j + 1);
            int s2 = __shfl_sync(0xffffffffu, sidx, j + 2);
            int s3 = __shfl_sync(0xffffffffu, sidx, j + 3);
            int s4 = __shfl_sync(0xffffffffu, sidx, j + 4);
            int s5 = __shfl_sync(0xffffffffu, sidx, j + 5);
            int s6 = __shfl_sync(0xffffffffu, sidx, j + 6);
            int s7 = __shfl_sync(0xffffffffu, sidx, j + 7);
            float w0 = __shfl_sync(0xffffffffu, w, j);
            float w1 = __shfl_sync(0xffffffffu, w, j + 1);
            float w2 = __shfl_sync(0xffffffffu, w, j + 2);
            float w3 = __shfl_sync(0xffffffffu, w, j + 3);
            float w4 = __shfl_sync(0xffffffffu, w, j + 4);
            float w5 = __shfl_sync(0xffffffffu, w, j + 5);
            float w6 = __shfl_sync(0xffffffffu, w, j + 6);
            float w7 = __shfl_sync(0xffffffffu, w, j + 7);
            float4 z0 = __ldg(&zrows[s0 * 32 + lane]);
            float4 z1 = __ldg(&zrows[s1 * 32 + lane]);
            float4 z2 = __ldg(&zrows[s2 * 32 + lane]);
            float4 z3 = __ldg(&zrows[s3 * 32 + lane]);
            float4 z4 = __ldg(&zrows[s4 * 32 + lane]);
            float4 z5 = __ldg(&zrows[s5 * 32 + lane]);
            float4 z6 = __ldg(&zrows[s6 * 32 + lane]);
            float4 z7 = __ldg(&zrows[s7 * 32 + lane]);
            ACC4(acc0, w0, z0) ACC4(acc1, w1, z1) ACC4(acc2, w2, z2) ACC4(acc3, w3, z3)
            ACC4(acc4, w4, z4) ACC4(acc5, w5, z5) ACC4(acc6, w6, z6) ACC4(acc7, w7, z7)
        }
        if (j + 4 <= deg) {
            int s0 = __shfl_sync(0xffffffffu, sidx, j);
            int s1 = __shfl_sync(0xffffffffu, sidx, j + 1);
            int s2 = __shfl_sync(0xffffffffu, sidx, j + 2);
            int s3 = __shfl_sync(0xffffffffu, sidx, j + 3);
            float w0 = __shfl_sync(0xffffffffu, w, j);
            float w1 = __shfl_sync(0xffffffffu, w, j + 1);
            float w2 = __shfl_sync(0xffffffffu, w, j + 2);
            float w3 = __shfl_sync(0xffffffffu, w, j + 3);
            float4 z0 = __ldg(&zrows[s0 * 32 + lane]);
            float4 z1 = __ldg(&zrows[s1 * 32 + lane]);
            float4 z2 = __ldg(&zrows[s2 * 32 + lane]);
            float4 z3 = __ldg(&zrows[s3 * 32 + lane]);
            ACC4(acc0, w0, z0) ACC4(acc1, w1, z1) ACC4(acc2, w2, z2) ACC4(acc3, w3, z3)
            j += 4;
        }
        for (; j < deg; j++) {
            int s0 = __shfl_sync(0xffffffffu, sidx, j);
            float w0 = __shfl_sync(0xffffffffu, w, j);
            float4 z0 = __ldg(&zrows[s0 * 32 + lane]);
            ACC4(acc0, w0, z0)
        }
        float inv = 1.f / d;
        o4.x = (acc0.x + acc1.x + acc2.x + acc3.x + acc4.x + acc5.x + acc6.x + acc7.x) * inv;
        o4.y = (acc0.y + acc1.y + acc2.y + acc3.y + acc4.y + acc5.y + acc6.y + acc7.y) * inv;
        o4.z = (acc0.z + acc1.z + acc2.z + acc3.z + acc4.z + acc5.z + acc6.z + acc7.z) * inv;
        o4.w = (acc0.w + acc1.w + acc2.w + acc3.w + acc4.w + acc5.w + acc6.w + acc7.w) * inv;
    } else if (deg > 32) {
        const float sdv = g_sdst[gw];
        float d = 0.f;
        for (int i = beg + lane; i < end; i += 32) {
            float e = __ldg(&g_ssrc[__ldg(&g_csr_src[i])]) + sdv;
            e = (e > 0.f) ? e : 0.01f * e;
            d += __expf(e);
        }
#pragma unroll
        for (int o = 16; o > 0; o >>= 1) d += __shfl_xor_sync(0xffffffffu, d, o);
        float4 acc = make_float4(0.f, 0.f, 0.f, 0.f);
        for (int i = beg; i < end; i++) {
            int s = __ldg(&g_csr_src[i]);
            float e = __ldg(&g_ssrc[s]) + sdv;
            e = (e > 0.f) ? e : 0.01f * e;
            float wv = __expf(e);
            float4 zr = __ldg(&zrows[s * 32 + lane]);
            ACC4(acc, wv, zr)
        }
        float inv = 1.f / d;
        o4.x = acc.x * inv; o4.y = acc.y * inv; o4.z = acc.z * inv; o4.w = acc.w * inv;
    }
    if (do_elu) {
        o4.x = (o4.x > 0.f) ? o4.x : (__expf(o4.x) - 1.f);
        o4.y = (o4.y > 0.f) ? o4.y : (__expf(o4.y) - 1.f);
        o4.z = (o4.z > 0.f) ? o4.z : (__expf(o4.z) - 1.f);
        o4.w = (o4.w > 0.f) ? o4.w : (__expf(o4.w) - 1.f);
    }
    ((float4*)g_x)[gw * 32 + lane] = o4;
}

// ---------------- mean readout ----------------
__global__ void reduce_kernel() {
    int c = threadIdx.x;
    float s = 0.f;
    for (int r = blockIdx.x; r < NNODES; r += gridDim.x) s += g_x[r * 128 + c];
    atomicAdd(&g_hg[c], s);
}

// ---------------- MLP readout: 128 -> 64 -> 32 -> 3 ----------------
__global__ void mlp_kernel(const float* __restrict__ M0w, const float* __restrict__ M0b,
                           const float* __restrict__ M1w, const float* __restrict__ M1b,
                           const float* __restrict__ M2w, const float* __restrict__ M2b,
                           float* __restrict__ out) {
    __shared__ float h0[128], h1[64], h2[32];
    int t = threadIdx.x;
    h0[t] = g_hg[t] * (1.0f / NNODES);
    __syncthreads();
    if (t < 64) {
        float s = M0b[t];
        for (int k = 0; k < 128; k++) s += h0[k] * M0w[k * 64 + t];
        h1[t] = fmaxf(s, 0.f);
    }
    __syncthreads();
    if (t < 32) {
        float s = M1b[t];
        for (int k = 0; k < 64; k++) s += h1[k] * M1w[k * 32 + t];
        h2[t] = fmaxf(s, 0.f);
    }
    __syncthreads();
    if (t < 3) {
        float s = M2b[t];
        for (int k = 0; k < 32; k++) s += h2[k] * M2w[k * 3 + t];
        out[t] = s;
    }
}

// ---------------- launch (single stream; agg is launch #6 for ncu -s 5) ------
extern "C" void kernel_launch(void* const* d_in, const int* in_sizes, int n_in,
                              void* d_out, int out_size) {
    const float* h   = (const float*)d_in[0];
    const int*   src = (const int*)d_in[1];
    const int*   dst = (const int*)d_in[2];
    const float* W0  = (const float*)d_in[3];
    const float* a0  = (const float*)d_in[4];
    const float* W1  = (const float*)d_in[5];
    const float* a1  = (const float*)d_in[6];
    const float* W2  = (const float*)d_in[7];
    const float* a2  = (const float*)d_in[8];
    const float* M0w = (const float*)d_in[9];
    const float* M0b = (const float*)d_in[10];
    const float* M1w = (const float*)d_in[11];
    const float* M1b = (const float*)d_in[12];
    const float* M2w = (const float*)d_in[13];
    const float* M2b = (const float*)d_in[14];
    float* out = (float*)d_out;

    float* zbuf;
    float* xbuf;
    void* degp;
    cudaGetSymbolAddress((void**)&zbuf, g_z);
    cudaGetSymbolAddress((void**)&xbuf, g_x);
    cudaGetSymbolAddress(&degp, g_deg);

    const int QB = (NEDGES / 4 + 255) / 256;
    const int WB = (NNODES * 32 + 255) / 256;
    const int GB = (NNODES + BM - 1) / BM;

    cudaMemsetAsync(degp, 0, NNODES * sizeof(int));        // launch 1
    hist_kernel<<<QB, 256>>>(dst);                          // launch 2
    scan_fused_kernel<<<SCAN_BLOCKS, 256>>>();              // launch 3 (zeros g_hg)
    scatter_kernel<<<QB, 256>>>(src, dst);                  // launch 4

    gemm_score_kernel<<<GB, 512>>>(h, W0, a0, zbuf, NNODES);   // launch 5
    agg_kernel<<<WB, 256>>>(1);                                 // launch 6 <- ncu
    gemm_score_kernel<<<GB, 512>>>(xbuf, W1, a1, zbuf, NNODES);
    agg_kernel<<<WB, 256>>>(1);
    gemm_score_kernel<<<GB, 512>>>(xbuf, W2, a2, zbuf, NNODES);
    agg_kernel<<<WB, 256>>>(0);

    reduce_kernel<<<512, 128>>>();
    mlp_kernel<<<1, 128>>>(M0w, M0b, M1w, M1b, M2w, M2b, out);
}

// round 14
// speedup vs baseline: 1.0520x; 1.0520x over previous
#include <cuda_runtime.h>
#include <cuda_bf16.h>
#include <cstdint>

#define NNODES 50000
#define NEDGES 800000
#define DIM 128
#define SCAN_BLOCKS ((NNODES + 255) / 256)   // 196

// ---------------- scratch (static __device__, no allocs) ----------------
__device__ float g_z[NNODES * DIM];
__device__ float g_x[NNODES * DIM];
__device__ float g_ssrc[NNODES];
__device__ float g_sdst[NNODES];
__device__ int   g_deg[NNODES];
__device__ int   g_off[NNODES + 1];
__device__ int   g_cur[NNODES];
__device__ int   g_csr_src[NEDGES];
__device__ int   g_bsum[SCAN_BLOCKS];
__device__ int   g_bbase[SCAN_BLOCKS + 1];
__device__ float g_hg[DIM];

// ---------------- CSR build (ILP-4 atomics) ----------------
__global__ void hist_kernel(const int* __restrict__ dst) {
    int q = blockIdx.x * blockDim.x + threadIdx.x;
    if (q * 4 < NEDGES) {
        int4 d4 = ((const int4*)dst)[q];
        atomicAdd(&g_deg[d4.x], 1);
        atomicAdd(&g_deg[d4.y], 1);
        atomicAdd(&g_deg[d4.z], 1);
        atomicAdd(&g_deg[d4.w], 1);
    }
}

__global__ void scan1_kernel() {
    __shared__ int sh[256];
    int i = blockIdx.x * 256 + threadIdx.x;
    int v = (i < NNODES) ? g_deg[i] : 0;
    sh[threadIdx.x] = v;
    __syncthreads();
    for (int o = 128; o > 0; o >>= 1) {
        if (threadIdx.x < o) sh[threadIdx.x] += sh[threadIdx.x + o];
        __syncthreads();
    }
    if (threadIdx.x == 0) g_bsum[blockIdx.x] = sh[0];
}

__global__ void scan2_kernel() {
    __shared__ int sh[256];
    int t = threadIdx.x;
    sh[t] = (t < SCAN_BLOCKS) ? g_bsum[t] : 0;
    __syncthreads();
    for (int o = 1; o < 256; o <<= 1) {
        int v = (t >= o) ? sh[t - o] : 0;
        __syncthreads();
        sh[t] += v;
        __syncthreads();
    }
    if (t < SCAN_BLOCKS) g_bbase[t] = (t == 0) ? 0 : sh[t - 1];
    if (t == 255) g_off[NNODES] = sh[SCAN_BLOCKS - 1];
}

__global__ void scan3_kernel() {
    __shared__ int sh[256];
    int t = threadIdx.x;
    int i = blockIdx.x * 256 + t;
    int v = (i < NNODES) ? g_deg[i] : 0;
    sh[t] = v;
    __syncthreads();
    for (int o = 1; o < 256; o <<= 1) {
        int u = (t >= o) ? sh[t - o] : 0;
        __syncthreads();
        sh[t] += u;
        __syncthreads();
    }
    if (i < NNODES) {
        int excl = g_bbase[blockIdx.x] + sh[t] - v;
        g_off[i] = excl;
        g_cur[i] = excl;
    }
}

__global__ void scatter_kernel(const int* __restrict__ src, const int* __restrict__ dst) {
    int q = blockIdx.x * blockDim.x + threadIdx.x;
    if (q * 4 < NEDGES) {
        int4 d4 = ((const int4*)dst)[q];
        int4 s4 = ((const int4*)src)[q];
        int p0 = atomicAdd(&g_cur[d4.x], 1);
        int p1 = atomicAdd(&g_cur[d4.y], 1);
        int p2 = atomicAdd(&g_cur[d4.z], 1);
        int p3 = atomicAdd(&g_cur[d4.w], 1);
        g_csr_src[p0] = s4.x;
        g_csr_src[p1] = s4.y;
        g_csr_src[p2] = s4.z;
        g_csr_src[p3] = s4.w;
    }
}

// ---------------- TF32 tensor-core GEMM + fused attention scores (R4-exact) ----
#define BM 128
#define BK 32
#define ASTRIDE 40
#define BSTRIDE 136

__device__ __forceinline__ uint32_t f2tf32(float f) {
    uint32_t u;
    asm("cvt.rna.tf32.f32 %0, %1;" : "=r"(u) : "f"(f));
    return u;
}

__device__ __forceinline__ void mma_tf32(float* d, uint32_t a0, uint32_t a1, uint32_t a2,
                                         uint32_t a3, uint32_t b0, uint32_t b1) {
    asm volatile(
        "mma.sync.aligned.m16n8k8.row.col.f32.tf32.tf32.f32 "
        "{%0,%1,%2,%3}, {%4,%5,%6,%7}, {%8,%9}, {%0,%1,%2,%3};\n"
        : "+f"(d[0]), "+f"(d[1]), "+f"(d[2]), "+f"(d[3])
        : "r"(a0), "r"(a1), "r"(a2), "r"(a3), "r"(b0), "r"(b1));
}

__global__ void __launch_bounds__(256) gemm_score_kernel(const float* __restrict__ A,
                                                         const float* __restrict__ W,
                                                         const float* __restrict__ att,
                                                         float* __restrict__ Z, int M) {
    __shared__ uint32_t As[BM * ASTRIDE];
    __shared__ uint32_t Bs[BK * BSTRIDE];
    const int tid = threadIdx.x;
    const int warp = tid >> 5;
    const int lane = tid & 31;
    const int gid = lane >> 2;
    const int tig = lane & 3;
    const int brow = blockIdx.x * BM;

    const int ar[4] = {(tid + 0) >> 3, (tid + 256) >> 3, (tid + 512) >> 3, (tid + 768) >> 3};
    const int ac = (tid & 7) * 4;
    const int br[4] = {(tid + 0) >> 5, (tid + 256) >> 5, (tid + 512) >> 5, (tid + 768) >> 5};
    const int bc = (tid & 31) * 4;

    float acc[16][4];
#pragma unroll
    for (int i = 0; i < 16; i++)
#pragma unroll
        for (int j = 0; j < 4; j++) acc[i][j] = 0.f;

    float4 pa[4], pb[4];
#pragma unroll
    for (int i = 0; i < 4; i++) {
        pa[i] = make_float4(0.f, 0.f, 0.f, 0.f);
        if (brow + ar[i] < M) pa[i] = *(const float4*)&A[(brow + ar[i]) * 128 + 0 + ac];
        pb[i] = *(const float4*)&W[br[i] * 128 + bc];
    }

#pragma unroll
    for (int t = 0; t < 4; t++) {
#pragma unroll
        for (int i = 0; i < 4; i++) {
            uint32_t* p = &As[ar[i] * ASTRIDE + ac];
            p[0] = f2tf32(pa[i].x); p[1] = f2tf32(pa[i].y);
            p[2] = f2tf32(pa[i].z); p[3] = f2tf32(pa[i].w);
            uint32_t* q = &Bs[br[i] * BSTRIDE + bc];
            q[0] = f2tf32(pb[i].x); q[1] = f2tf32(pb[i].y);
            q[2] = f2tf32(pb[i].z); q[3] = f2tf32(pb[i].w);
        }
        __syncthreads();
        if (t < 3) {
            int k0 = (t + 1) * BK;
#pragma unroll
            for (int i = 0; i < 4; i++) {
                pa[i] = make_float4(0.f, 0.f, 0.f, 0.f);
                if (brow + ar[i] < M) pa[i] = *(const float4*)&A[(brow + ar[i]) * 128 + k0 + ac];
                pb[i] = *(const float4*)&W[(k0 + br[i]) * 128 + bc];
            }
        }
#pragma unroll
        for (int kk = 0; kk < 4; kk++) {
            const int wrow = warp * 16;
            uint32_t a0 = As[(wrow + gid) * ASTRIDE + kk * 8 + tig];
            uint32_t a1 = As[(wrow + gid + 8) * ASTRIDE + kk * 8 + tig];
            uint32_t a2 = As[(wrow + gid) * ASTRIDE + kk * 8 + tig + 4];
            uint32_t a3 = As[(wrow + gid + 8) * ASTRIDE + kk * 8 + tig + 4];
#pragma unroll
            for (int nt = 0; nt < 16; nt++) {
                uint32_t b0 = Bs[(kk * 8 + tig) * BSTRIDE + nt * 8 + gid];
                uint32_t b1 = Bs[(kk * 8 + tig + 4) * BSTRIDE + nt * 8 + gid];
                mma_tf32(acc[nt], a0, a1, a2, a3, b0, b1);
            }
        }
        __syncthreads();
    }

    const int r0 = brow + warp * 16 + gid;
    const int r1 = r0 + 8;
    float s1a = 0.f, s2a = 0.f, s1b = 0.f, s2b = 0.f;
#pragma unroll
    for (int nt = 0; nt < 16; nt++) {
        int col = nt * 8 + tig * 2;
        float al0 = __ldg(&att[col]);
        float al1 = __ldg(&att[col + 1]);
        float ah0 = __ldg(&att[128 + col]);
        float ah1 = __ldg(&att[128 + col + 1]);
        if (r0 < M) *(float2*)&Z[r0 * 128 + col] = make_float2(acc[nt][0], acc[nt][1]);
        if (r1 < M) *(float2*)&Z[r1 * 128 + col] = make_float2(acc[nt][2], acc[nt][3]);
        s1a += acc[nt][0] * al0 + acc[nt][1] * al1;
        s2a += acc[nt][0] * ah0 + acc[nt][1] * ah1;
        s1b += acc[nt][2] * al0 + acc[nt][3] * al1;
        s2b += acc[nt][2] * ah0 + acc[nt][3] * ah1;
    }
#pragma unroll
    for (int o = 1; o <= 2; o <<= 1) {
        s1a += __shfl_xor_sync(0xffffffffu, s1a, o);
        s2a += __shfl_xor_sync(0xffffffffu, s2a, o);
        s1b += __shfl_xor_sync(0xffffffffu, s1b, o);
        s2b += __shfl_xor_sync(0xffffffffu, s2b, o);
    }
    if (tig == 0) {
        if (r0 < M) { g_ssrc[r0] = s1a; g_sdst[r0] = s2a; }
        if (r1 < M) { g_ssrc[r1] = s1b; g_sdst[r1] = s2b; }
    }
}

// ---------------- fused softmax + aggregation (one warp per dst node) --------
// deg<=32: ILP-8 batched z-row gathers.
#define ACC4(A, W4, Z4) \
    A.x += W4 * Z4.x; A.y += W4 * Z4.y; A.z += W4 * Z4.z; A.w += W4 * Z4.w;

__global__ void agg_kernel(int do_elu) {
    int gw = (blockIdx.x * blockDim.x + threadIdx.x) >> 5;
    int lane = threadIdx.x & 31;
    if (gw >= NNODES) return;
    const int beg = g_off[gw];
    const int end = g_off[gw + 1];
    const int deg = end - beg;
    const float4* zrows = (const float4*)g_z;

    float4 o4 = make_float4(0.f, 0.f, 0.f, 0.f);
    if (deg > 0 && deg <= 32) {
        int sidx = 0;
        float w = 0.f;
        if (lane < deg) {
            sidx = __ldg(&g_csr_src[beg + lane]);
            float e = __ldg(&g_ssrc[sidx]) + g_sdst[gw];
            e = (e > 0.f) ? e : 0.01f * e;
            w = __expf(e);
        }
        float d = w;
#pragma unroll
        for (int o = 16; o > 0; o >>= 1) d += __shfl_xor_sync(0xffffffffu, d, o);

        float4 acc0 = make_float4(0.f, 0.f, 0.f, 0.f);
        float4 acc1 = make_float4(0.f, 0.f, 0.f, 0.f);
        float4 acc2 = make_float4(0.f, 0.f, 0.f, 0.f);
        float4 acc3 = make_float4(0.f, 0.f, 0.f, 0.f);
        float4 acc4 = make_float4(0.f, 0.f, 0.f, 0.f);
        float4 acc5 = make_float4(0.f, 0.f, 0.f, 0.f);
        float4 acc6 = make_float4(0.f, 0.f, 0.f, 0.f);
        float4 acc7 = make_float4(0.f, 0.f, 0.f, 0.f);
        int j = 0;
        for (; j + 8 <= deg; j += 8) {
            int s0 = __shfl_sync(0xffffffffu, sidx, j);
            int s1 = __shfl_sync(0xffffffffu, sidx, j + 1);
            int s2 = __shfl_sync(0xffffffffu, sidx, j + 2);
            int s3 = __shfl_sync(0xffffffffu, sidx, j + 3);
            int s4 = __shfl_sync(0xffffffffu, sidx, j + 4);
            int s5 = __shfl_sync(0xffffffffu, sidx, j + 5);
            int s6 = __shfl_sync(0xffffffffu, sidx, j + 6);
            int s7 = __shfl_sync(0xffffffffu, sidx, j + 7);
            float w0 = __shfl_sync(0xffffffffu, w, j);
            float w1 = __shfl_sync(0xffffffffu, w, j + 1);
            float w2 = __shfl_sync(0xffffffffu, w, j + 2);
            float w3 = __shfl_sync(0xffffffffu, w, j + 3);
            float w4 = __shfl_sync(0xffffffffu, w, j + 4);
            float w5 = __shfl_sync(0xffffffffu, w, j + 5);
            float w6 = __shfl_sync(0xffffffffu, w, j + 6);
            float w7 = __shfl_sync(0xffffffffu, w, j + 7);
            float4 z0 = __ldg(&zrows[s0 * 32 + lane]);
            float4 z1 = __ldg(&zrows[s1 * 32 + lane]);
            float4 z2 = __ldg(&zrows[s2 * 32 + lane]);
            float4 z3 = __ldg(&zrows[s3 * 32 + lane]);
            float4 z4 = __ldg(&zrows[s4 * 32 + lane]);
            float4 z5 = __ldg(&zrows[s5 * 32 + lane]);
            float4 z6 = __ldg(&zrows[s6 * 32 + lane]);
            float4 z7 = __ldg(&zrows[s7 * 32 + lane]);
            ACC4(acc0, w0, z0) ACC4(acc1, w1, z1) ACC4(acc2, w2, z2) ACC4(acc3, w3, z3)
            ACC4(acc4, w4, z4) ACC4(acc5, w5, z5) ACC4(acc6, w6, z6) ACC4(acc7, w7, z7)
        }
        if (j + 4 <= deg) {
            int s0 = __shfl_sync(0xffffffffu, sidx, j);
            int s1 = __shfl_sync(0xffffffffu, sidx, j + 1);
            int s2 = __shfl_sync(0xffffffffu, sidx, j + 2);
            int s3 = __shfl_sync(0xffffffffu, sidx, j + 3);
            float w0 = __shfl_sync(0xffffffffu, w, j);
            float w1 = __shfl_sync(0xffffffffu, w, j + 1);
            float w2 = __shfl_sync(0xffffffffu, w, j + 2);
            float w3 = __shfl_sync(0xffffffffu, w, j + 3);
            float4 z0 = __ldg(&zrows[s0 * 32 + lane]);
            float4 z1 = __ldg(&zrows[s1 * 32 + lane]);
            float4 z2 = __ldg(&zrows[s2 * 32 + lane]);
            float4 z3 = __ldg(&zrows[s3 * 32 + lane]);
            ACC4(acc0, w0, z0) ACC4(acc1, w1, z1) ACC4(acc2, w2, z2) ACC4(acc3, w3, z3)
            j += 4;
        }
        for (; j < deg; j++) {
            int s0 = __shfl_sync(0xffffffffu, sidx, j);
            float w0 = __shfl_sync(0xffffffffu, w, j);
            float4 z0 = __ldg(&zrows[s0 * 32 + lane]);
            ACC4(acc0, w0, z0)
        }
        float inv = 1.f / d;
        o4.x = (acc0.x + acc1.x + acc2.x + acc3.x + acc4.x + acc5.x + acc6.x + acc7.x) * inv;
        o4.y = (acc0.y + acc1.y + acc2.y + acc3.y + acc4.y + acc5.y + acc6.y + acc7.y) * inv;
        o4.z = (acc0.z + acc1.z + acc2.z + acc3.z + acc4.z + acc5.z + acc6.z + acc7.z) * inv;
        o4.w = (acc0.w + acc1.w + acc2.w + acc3.w + acc4.w + acc5.w + acc6.w + acc7.w) * inv;
    } else if (deg > 32) {
        const float sdv = g_sdst[gw];
        float d = 0.f;
        for (int i = beg + lane; i < end; i += 32) {
            float e = __ldg(&g_ssrc[__ldg(&g_csr_src[i])]) + sdv;
            e = (e > 0.f) ? e : 0.01f * e;
            d += __expf(e);
        }
#pragma unroll
        for (int o = 16; o > 0; o >>= 1) d += __shfl_xor_sync(0xffffffffu, d, o);
        float4 acc = make_float4(0.f, 0.f, 0.f, 0.f);
        for (int i = beg; i < end; i++) {
            int s = __ldg(&g_csr_src[i]);
            float e = __ldg(&g_ssrc[s]) + sdv;
            e = (e > 0.f) ? e : 0.01f * e;
            float wv = __expf(e);
            float4 zr = __ldg(&zrows[s * 32 + lane]);
            ACC4(acc, wv, zr)
        }
        float inv = 1.f / d;
        o4.x = acc.x * inv; o4.y = acc.y * inv; o4.z = acc.z * inv; o4.w = acc.w * inv;
    }
    if (do_elu) {
        o4.x = (o4.x > 0.f) ? o4.x : (__expf(o4.x) - 1.f);
        o4.y = (o4.y > 0.f) ? o4.y : (__expf(o4.y) - 1.f);
        o4.z = (o4.z > 0.f) ? o4.z : (__expf(o4.z) - 1.f);
        o4.w = (o4.w > 0.f) ? o4.w : (__expf(o4.w) - 1.f);
    }
    ((float4*)g_x)[gw * 32 + lane] = o4;
}

// ---------------- mean readout ----------------
__global__ void reduce_kernel() {
    int c = threadIdx.x;
    float s = 0.f;
    for (int r = blockIdx.x; r < NNODES; r += gridDim.x) s += g_x[r * 128 + c];
    atomicAdd(&g_hg[c], s);
}

// ---------------- MLP readout: 128 -> 64 -> 32 -> 3 ----------------
__global__ void mlp_kernel(const float* __restrict__ M0w, const float* __restrict__ M0b,
                           const float* __restrict__ M1w, const float* __restrict__ M1b,
                           const float* __restrict__ M2w, const float* __restrict__ M2b,
                           float* __restrict__ out) {
    __shared__ float h0[128], h1[64], h2[32];
    int t = threadIdx.x;
    h0[t] = g_hg[t] * (1.0f / NNODES);
    __syncthreads();
    if (t < 64) {
        float s = M0b[t];
        for (int k = 0; k < 128; k++) s += h0[k] * M0w[k * 64 + t];
        h1[t] = fmaxf(s, 0.f);
    }
    __syncthreads();
    if (t < 32) {
        float s = M1b[t];
        for (int k = 0; k < 64; k++) s += h1[k] * M1w[k * 32 + t];
        h2[t] = fmaxf(s, 0.f);
    }
    __syncthreads();
    if (t < 3) {
        float s = M2b[t];
        for (int k = 0; k < 32; k++) s += h2[k] * M2w[k * 3 + t];
        out[t] = s;
    }
}

// ---------------- launch: CSR forked onto side stream (R5 structure) --------
extern "C" void kernel_launch(void* const* d_in, const int* in_sizes, int n_in,
                              void* d_out, int out_size) {
    const float* h   = (const float*)d_in[0];
    const int*   src = (const int*)d_in[1];
    const int*   dst = (const int*)d_in[2];
    const float* W0  = (const float*)d_in[3];
    const float* a0  = (const float*)d_in[4];
    const float* W1  = (const float*)d_in[5];
    const float* a1  = (const float*)d_in[6];
    const float* W2  = (const float*)d_in[7];
    const float* a2  = (const float*)d_in[8];
    const float* M0w = (const float*)d_in[9];
    const float* M0b = (const float*)d_in[10];
    const float* M1w = (const float*)d_in[11];
    const float* M1b = (const float*)d_in[12];
    const float* M2w = (const float*)d_in[13];
    const float* M2b = (const float*)d_in[14];
    float* out = (float*)d_out;

    float* zbuf;
    float* xbuf;
    void* degp;
    void* hgp;
    cudaGetSymbolAddress((void**)&zbuf, g_z);
    cudaGetSymbolAddress((void**)&xbuf, g_x);
    cudaGetSymbolAddress(&degp, g_deg);
    cudaGetSymbolAddress(&hgp, g_hg);

    const int QB = (NEDGES / 4 + 255) / 256;
    const int WB = (NNODES * 32 + 255) / 256;
    const int GB = (NNODES + BM - 1) / BM;

    cudaStream_t s2;
    cudaStreamCreateWithFlags(&s2, cudaStreamNonBlocking);
    cudaEvent_t eFork, eCsr;
    cudaEventCreateWithFlags(&eFork, cudaEventDisableTiming);
    cudaEventCreateWithFlags(&eCsr, cudaEventDisableTiming);

    cudaEventRecord(eFork, 0);
    cudaStreamWaitEvent(s2, eFork, 0);

    // CSR branch (side stream)
    cudaMemsetAsync(degp, 0, NNODES * sizeof(int), s2);
    hist_kernel<<<QB, 256, 0, s2>>>(dst);
    scan1_kernel<<<SCAN_BLOCKS, 256, 0, s2>>>();
    scan2_kernel<<<1, 256, 0, s2>>>();
    scan3_kernel<<<SCAN_BLOCKS, 256, 0, s2>>>();
    scatter_kernel<<<QB, 256, 0, s2>>>(src, dst);
    cudaEventRecord(eCsr, s2);

    // main branch
    cudaMemsetAsync(hgp, 0, DIM * sizeof(float));
    gemm_score_kernel<<<GB, 256>>>(h, W0, a0, zbuf, NNODES);
    cudaStreamWaitEvent(0, eCsr, 0);
    agg_kernel<<<WB, 256>>>(1);
    gemm_score_kernel<<<GB, 256>>>(xbuf, W1, a1, zbuf, NNODES);
    agg_kernel<<<WB, 256>>>(1);
    gemm_score_kernel<<<GB, 256>>>(xbuf, W2, a2, zbuf, NNODES);
    agg_kernel<<<WB, 256>>>(0);

    reduce_kernel<<<512, 128>>>();
    mlp_kernel<<<1, 128>>>(M0w, M0b, M1w, M1b, M2w, M2b, out);

    cudaEventDestroy(eFork);
    cudaEventDestroy(eCsr);
    cudaStreamDestroy(s2);
}

// round 15
// speedup vs baseline: 1.1653x; 1.1077x over previous
#include <cuda_runtime.h>
#include <cuda_bf16.h>
#include <cstdint>

#define NNODES 50000
#define NEDGES 800000
#define DIM 128
#define SCAN_BLOCKS ((NNODES + 255) / 256)   // 196

// ---------------- scratch (static __device__, no allocs) ----------------
__device__ float g_z[NNODES * DIM];
__device__ float g_x[NNODES * DIM];
__device__ float g_ssrc[NNODES];
__device__ float g_sdst[NNODES];
__device__ int   g_deg[NNODES];
__device__ int   g_off[NNODES + 1];
__device__ int   g_cur[NNODES];
__device__ int   g_csr_src[NEDGES];
__device__ int   g_bsum[SCAN_BLOCKS];
__device__ int   g_bbase[SCAN_BLOCKS + 1];
__device__ float g_hg[DIM];

// ---------------- CSR build (ILP-4 atomics) ----------------
__global__ void hist_kernel(const int* __restrict__ dst) {
    int q = blockIdx.x * blockDim.x + threadIdx.x;
    if (q * 4 < NEDGES) {
        int4 d4 = ((const int4*)dst)[q];
        atomicAdd(&g_deg[d4.x], 1);
        atomicAdd(&g_deg[d4.y], 1);
        atomicAdd(&g_deg[d4.z], 1);
        atomicAdd(&g_deg[d4.w], 1);
    }
}

__global__ void scan1_kernel() {
    __shared__ int sh[256];
    int i = blockIdx.x * 256 + threadIdx.x;
    int v = (i < NNODES) ? g_deg[i] : 0;
    sh[threadIdx.x] = v;
    __syncthreads();
    for (int o = 128; o > 0; o >>= 1) {
        if (threadIdx.x < o) sh[threadIdx.x] += sh[threadIdx.x + o];
        __syncthreads();
    }
    if (threadIdx.x == 0) g_bsum[blockIdx.x] = sh[0];
}

__global__ void scan2_kernel() {
    __shared__ int sh[256];
    int t = threadIdx.x;
    sh[t] = (t < SCAN_BLOCKS) ? g_bsum[t] : 0;
    __syncthreads();
    for (int o = 1; o < 256; o <<= 1) {
        int v = (t >= o) ? sh[t - o] : 0;
        __syncthreads();
        sh[t] += v;
        __syncthreads();
    }
    if (t < SCAN_BLOCKS) g_bbase[t] = (t == 0) ? 0 : sh[t - 1];
    if (t == 255) g_off[NNODES] = sh[SCAN_BLOCKS - 1];
}

__global__ void scan3_kernel() {
    __shared__ int sh[256];
    int t = threadIdx.x;
    int i = blockIdx.x * 256 + t;
    int v = (i < NNODES) ? g_deg[i] : 0;
    sh[t] = v;
    __syncthreads();
    for (int o = 1; o < 256; o <<= 1) {
        int u = (t >= o) ? sh[t - o] : 0;
        __syncthreads();
        sh[t] += u;
        __syncthreads();
    }
    if (i < NNODES) {
        int excl = g_bbase[blockIdx.x] + sh[t] - v;
        g_off[i] = excl;
        g_cur[i] = excl;
    }
}

__global__ void scatter_kernel(const int* __restrict__ src, const int* __restrict__ dst) {
    int q = blockIdx.x * blockDim.x + threadIdx.x;
    if (q * 4 < NEDGES) {
        int4 d4 = ((const int4*)dst)[q];
        int4 s4 = ((const int4*)src)[q];
        int p0 = atomicAdd(&g_cur[d4.x], 1);
        int p1 = atomicAdd(&g_cur[d4.y], 1);
        int p2 = atomicAdd(&g_cur[d4.z], 1);
        int p3 = atomicAdd(&g_cur[d4.w], 1);
        g_csr_src[p0] = s4.x;
        g_csr_src[p1] = s4.y;
        g_csr_src[p2] = s4.z;
        g_csr_src[p3] = s4.w;
    }
}

// ---------------- TF32 tensor-core GEMM + fused attention scores (R4-exact) ----
#define BM 128
#define BK 32
#define ASTRIDE 40
#define BSTRIDE 136

__device__ __forceinline__ uint32_t f2tf32(float f) {
    uint32_t u;
    asm("cvt.rna.tf32.f32 %0, %1;" : "=r"(u) : "f"(f));
    return u;
}

__device__ __forceinline__ void mma_tf32(float* d, uint32_t a0, uint32_t a1, uint32_t a2,
                                         uint32_t a3, uint32_t b0, uint32_t b1) {
    asm volatile(
        "mma.sync.aligned.m16n8k8.row.col.f32.tf32.tf32.f32 "
        "{%0,%1,%2,%3}, {%4,%5,%6,%7}, {%8,%9}, {%0,%1,%2,%3};\n"
        : "+f"(d[0]), "+f"(d[1]), "+f"(d[2]), "+f"(d[3])
        : "r"(a0), "r"(a1), "r"(a2), "r"(a3), "r"(b0), "r"(b1));
}

__global__ void __launch_bounds__(256) gemm_score_kernel(const float* __restrict__ A,
                                                         const float* __restrict__ W,
                                                         const float* __restrict__ att,
                                                         float* __restrict__ Z, int M) {
    __shared__ uint32_t As[BM * ASTRIDE];
    __shared__ uint32_t Bs[BK * BSTRIDE];
    const int tid = threadIdx.x;
    const int warp = tid >> 5;
    const int lane = tid & 31;
    const int gid = lane >> 2;
    const int tig = lane & 3;
    const int brow = blockIdx.x * BM;

    const int ar[4] = {(tid + 0) >> 3, (tid + 256) >> 3, (tid + 512) >> 3, (tid + 768) >> 3};
    const int ac = (tid & 7) * 4;
    const int br[4] = {(tid + 0) >> 5, (tid + 256) >> 5, (tid + 512) >> 5, (tid + 768) >> 5};
    const int bc = (tid & 31) * 4;

    float acc[16][4];
#pragma unroll
    for (int i = 0; i < 16; i++)
#pragma unroll
        for (int j = 0; j < 4; j++) acc[i][j] = 0.f;

    float4 pa[4], pb[4];
#pragma unroll
    for (int i = 0; i < 4; i++) {
        pa[i] = make_float4(0.f, 0.f, 0.f, 0.f);
        if (brow + ar[i] < M) pa[i] = *(const float4*)&A[(brow + ar[i]) * 128 + 0 + ac];
        pb[i] = *(const float4*)&W[br[i] * 128 + bc];
    }

#pragma unroll
    for (int t = 0; t < 4; t++) {
#pragma unroll
        for (int i = 0; i < 4; i++) {
            uint32_t* p = &As[ar[i] * ASTRIDE + ac];
            p[0] = f2tf32(pa[i].x); p[1] = f2tf32(pa[i].y);
            p[2] = f2tf32(pa[i].z); p[3] = f2tf32(pa[i].w);
            uint32_t* q = &Bs[br[i] * BSTRIDE + bc];
            q[0] = f2tf32(pb[i].x); q[1] = f2tf32(pb[i].y);
            q[2] = f2tf32(pb[i].z); q[3] = f2tf32(pb[i].w);
        }
        __syncthreads();
        if (t < 3) {
            int k0 = (t + 1) * BK;
#pragma unroll
            for (int i = 0; i < 4; i++) {
                pa[i] = make_float4(0.f, 0.f, 0.f, 0.f);
                if (brow + ar[i] < M) pa[i] = *(const float4*)&A[(brow + ar[i]) * 128 + k0 + ac];
                pb[i] = *(const float4*)&W[(k0 + br[i]) * 128 + bc];
            }
        }
#pragma unroll
        for (int kk = 0; kk < 4; kk++) {
            const int wrow = warp * 16;
            uint32_t a0 = As[(wrow + gid) * ASTRIDE + kk * 8 + tig];
            uint32_t a1 = As[(wrow + gid + 8) * ASTRIDE + kk * 8 + tig];
            uint32_t a2 = As[(wrow + gid) * ASTRIDE + kk * 8 + tig + 4];
            uint32_t a3 = As[(wrow + gid + 8) * ASTRIDE + kk * 8 + tig + 4];
#pragma unroll
            for (int nt = 0; nt < 16; nt++) {
                uint32_t b0 = Bs[(kk * 8 + tig) * BSTRIDE + nt * 8 + gid];
                uint32_t b1 = Bs[(kk * 8 + tig + 4) * BSTRIDE + nt * 8 + gid];
                mma_tf32(acc[nt], a0, a1, a2, a3, b0, b1);
            }
        }
        __syncthreads();
    }

    const int r0 = brow + warp * 16 + gid;
    const int r1 = r0 + 8;
    float s1a = 0.f, s2a = 0.f, s1b = 0.f, s2b = 0.f;
#pragma unroll
    for (int nt = 0; nt < 16; nt++) {
        int col = nt * 8 + tig * 2;
        float al0 = __ldg(&att[col]);
        float al1 = __ldg(&att[col + 1]);
        float ah0 = __ldg(&att[128 + col]);
        float ah1 = __ldg(&att[128 + col + 1]);
        if (r0 < M) *(float2*)&Z[r0 * 128 + col] = make_float2(acc[nt][0], acc[nt][1]);
        if (r1 < M) *(float2*)&Z[r1 * 128 + col] = make_float2(acc[nt][2], acc[nt][3]);
        s1a += acc[nt][0] * al0 + acc[nt][1] * al1;
        s2a += acc[nt][0] * ah0 + acc[nt][1] * ah1;
        s1b += acc[nt][2] * al0 + acc[nt][3] * al1;
        s2b += acc[nt][2] * ah0 + acc[nt][3] * ah1;
    }
#pragma unroll
    for (int o = 1; o <= 2; o <<= 1) {
        s1a += __shfl_xor_sync(0xffffffffu, s1a, o);
        s2a += __shfl_xor_sync(0xffffffffu, s2a, o);
        s1b += __shfl_xor_sync(0xffffffffu, s1b, o);
        s2b += __shfl_xor_sync(0xffffffffu, s2b, o);
    }
    if (tig == 0) {
        if (r0 < M) { g_ssrc[r0] = s1a; g_sdst[r0] = s2a; }
        if (r1 < M) { g_ssrc[r1] = s1b; g_sdst[r1] = s2b; }
    }
}

// ---------------- fused softmax + aggregation (one warp per dst node) --------
// deg<=32: ILP-4 batched z-row gathers (empirical sweet spot).
__global__ void agg_kernel(int do_elu) {
    int gw = (blockIdx.x * blockDim.x + threadIdx.x) >> 5;
    int lane = threadIdx.x & 31;
    if (gw >= NNODES) return;
    const int beg = g_off[gw];
    const int end = g_off[gw + 1];
    const int deg = end - beg;
    const float4* zrows = (const float4*)g_z;

    float4 o4 = make_float4(0.f, 0.f, 0.f, 0.f);
    if (deg > 0 && deg <= 32) {
        int sidx = 0;
        float w = 0.f;
        if (lane < deg) {
            sidx = __ldg(&g_csr_src[beg + lane]);
            float e = __ldg(&g_ssrc[sidx]) + g_sdst[gw];
            e = (e > 0.f) ? e : 0.01f * e;
            w = __expf(e);
        }
        float d = w;
#pragma unroll
        for (int o = 16; o > 0; o >>= 1) d += __shfl_xor_sync(0xffffffffu, d, o);

        float4 acc0 = make_float4(0.f, 0.f, 0.f, 0.f);
        float4 acc1 = make_float4(0.f, 0.f, 0.f, 0.f);
        float4 acc2 = make_float4(0.f, 0.f, 0.f, 0.f);
        float4 acc3 = make_float4(0.f, 0.f, 0.f, 0.f);
        int j = 0;
        for (; j + 4 <= deg; j += 4) {
            int s0 = __shfl_sync(0xffffffffu, sidx, j);
            int s1 = __shfl_sync(0xffffffffu, sidx, j + 1);
            int s2 = __shfl_sync(0xffffffffu, sidx, j + 2);
            int s3 = __shfl_sync(0xffffffffu, sidx, j + 3);
            float w0 = __shfl_sync(0xffffffffu, w, j);
            float w1 = __shfl_sync(0xffffffffu, w, j + 1);
            float w2 = __shfl_sync(0xffffffffu, w, j + 2);
            float w3 = __shfl_sync(0xffffffffu, w, j + 3);
            float4 z0 = __ldg(&zrows[s0 * 32 + lane]);
            float4 z1 = __ldg(&zrows[s1 * 32 + lane]);
            float4 z2 = __ldg(&zrows[s2 * 32 + lane]);
            float4 z3 = __ldg(&zrows[s3 * 32 + lane]);
            acc0.x += w0 * z0.x; acc0.y += w0 * z0.y; acc0.z += w0 * z0.z; acc0.w += w0 * z0.w;
            acc1.x += w1 * z1.x; acc1.y += w1 * z1.y; acc1.z += w1 * z1.z; acc1.w += w1 * z1.w;
            acc2.x += w2 * z2.x; acc2.y += w2 * z2.y; acc2.z += w2 * z2.z; acc2.w += w2 * z2.w;
            acc3.x += w3 * z3.x; acc3.y += w3 * z3.y; acc3.z += w3 * z3.z; acc3.w += w3 * z3.w;
        }
        for (; j < deg; j++) {
            int s0 = __shfl_sync(0xffffffffu, sidx, j);
            float w0 = __shfl_sync(0xffffffffu, w, j);
            float4 z0 = __ldg(&zrows[s0 * 32 + lane]);
            acc0.x += w0 * z0.x; acc0.y += w0 * z0.y; acc0.z += w0 * z0.z; acc0.w += w0 * z0.w;
        }
        float inv = 1.f / d;
        o4.x = (acc0.x + acc1.x + acc2.x + acc3.x) * inv;
        o4.y = (acc0.y + acc1.y + acc2.y + acc3.y) * inv;
        o4.z = (acc0.z + acc1.z + acc2.z + acc3.z) * inv;
        o4.w = (acc0.w + acc1.w + acc2.w + acc3.w) * inv;
    } else if (deg > 32) {
        const float sdv = g_sdst[gw];
        float d = 0.f;
        for (int i = beg + lane; i < end; i += 32) {
            float e = __ldg(&g_ssrc[__ldg(&g_csr_src[i])]) + sdv;
            e = (e > 0.f) ? e : 0.01f * e;
            d += __expf(e);
        }
#pragma unroll
        for (int o = 16; o > 0; o >>= 1) d += __shfl_xor_sync(0xffffffffu, d, o);
        float4 acc = make_float4(0.f, 0.f, 0.f, 0.f);
        for (int i = beg; i < end; i++) {
            int s = __ldg(&g_csr_src[i]);
            float e = __ldg(&g_ssrc[s]) + sdv;
            e = (e > 0.f) ? e : 0.01f * e;
            float wv = __expf(e);
            float4 zr = __ldg(&zrows[s * 32 + lane]);
            acc.x += wv * zr.x; acc.y += wv * zr.y; acc.z += wv * zr.z; acc.w += wv * zr.w;
        }
        float inv = 1.f / d;
        o4.x = acc.x * inv; o4.y = acc.y * inv; o4.z = acc.z * inv; o4.w = acc.w * inv;
    }
    if (do_elu) {
        o4.x = (o4.x > 0.f) ? o4.x : (__expf(o4.x) - 1.f);
        o4.y = (o4.y > 0.f) ? o4.y : (__expf(o4.y) - 1.f);
        o4.z = (o4.z > 0.f) ? o4.z : (__expf(o4.z) - 1.f);
        o4.w = (o4.w > 0.f) ? o4.w : (__expf(o4.w) - 1.f);
    }
    ((float4*)g_x)[gw * 32 + lane] = o4;
}

// ---------------- mean readout ----------------
__global__ void reduce_kernel() {
    int c = threadIdx.x;
    float s = 0.f;
    for (int r = blockIdx.x; r < NNODES; r += gridDim.x) s += g_x[r * 128 + c];
    atomicAdd(&g_hg[c], s);
}

// ---------------- MLP readout: 128 -> 64 -> 32 -> 3 ----------------
__global__ void mlp_kernel(const float* __restrict__ M0w, const float* __restrict__ M0b,
                           const float* __restrict__ M1w, const float* __restrict__ M1b,
                           const float* __restrict__ M2w, const float* __restrict__ M2b,
                           float* __restrict__ out) {
    __shared__ float h0[128], h1[64], h2[32];
    int t = threadIdx.x;
    h0[t] = g_hg[t] * (1.0f / NNODES);
    __syncthreads();
    if (t < 64) {
        float s = M0b[t];
        for (int k = 0; k < 128; k++) s += h0[k] * M0w[k * 64 + t];
        h1[t] = fmaxf(s, 0.f);
    }
    __syncthreads();
    if (t < 32) {
        float s = M1b[t];
        for (int k = 0; k < 64; k++) s += h1[k] * M1w[k * 32 + t];
        h2[t] = fmaxf(s, 0.f);
    }
    __syncthreads();
    if (t < 3) {
        float s = M2b[t];
        for (int k = 0; k < 32; k++) s += h2[k] * M2w[k * 3 + t];
        out[t] = s;
    }
}

// ---------------- launch: CSR forked onto side stream (R5 structure) --------
extern "C" void kernel_launch(void* const* d_in, const int* in_sizes, int n_in,
                              void* d_out, int out_size) {
    const float* h   = (const float*)d_in[0];
    const int*   src = (const int*)d_in[1];
    const int*   dst = (const int*)d_in[2];
    const float* W0  = (const float*)d_in[3];
    const float* a0  = (const float*)d_in[4];
    const float* W1  = (const float*)d_in[5];
    const float* a1  = (const float*)d_in[6];
    const float* W2  = (const float*)d_in[7];
    const float* a2  = (const float*)d_in[8];
    const float* M0w = (const float*)d_in[9];
    const float* M0b = (const float*)d_in[10];
    const float* M1w = (const float*)d_in[11];
    const float* M1b = (const float*)d_in[12];
    const float* M2w = (const float*)d_in[13];
    const float* M2b = (const float*)d_in[14];
    float* out = (float*)d_out;

    float* zbuf;
    float* xbuf;
    void* degp;
    void* hgp;
    cudaGetSymbolAddress((void**)&zbuf, g_z);
    cudaGetSymbolAddress((void**)&xbuf, g_x);
    cudaGetSymbolAddress(&degp, g_deg);
    cudaGetSymbolAddress(&hgp, g_hg);

    const int QB = (NEDGES / 4 + 255) / 256;
    const int WB = (NNODES * 32 + 255) / 256;
    const int GB = (NNODES + BM - 1) / BM;

    cudaStream_t s2;
    cudaStreamCreateWithFlags(&s2, cudaStreamNonBlocking);
    cudaEvent_t eFork, eCsr;
    cudaEventCreateWithFlags(&eFork, cudaEventDisableTiming);
    cudaEventCreateWithFlags(&eCsr, cudaEventDisableTiming);

    cudaEventRecord(eFork, 0);
    cudaStreamWaitEvent(s2, eFork, 0);

    // CSR branch (side stream)
    cudaMemsetAsync(degp, 0, NNODES * sizeof(int), s2);
    hist_kernel<<<QB, 256, 0, s2>>>(dst);
    scan1_kernel<<<SCAN_BLOCKS, 256, 0, s2>>>();
    scan2_kernel<<<1, 256, 0, s2>>>();
    scan3_kernel<<<SCAN_BLOCKS, 256, 0, s2>>>();
    scatter_kernel<<<QB, 256, 0, s2>>>(src, dst);
    cudaEventRecord(eCsr, s2);

    // main branch
    cudaMemsetAsync(hgp, 0, DIM * sizeof(float));
    gemm_score_kernel<<<GB, 256>>>(h, W0, a0, zbuf, NNODES);
    cudaStreamWaitEvent(0, eCsr, 0);
    agg_kernel<<<WB, 256>>>(1);
    gemm_score_kernel<<<GB, 256>>>(xbuf, W1, a1, zbuf, NNODES);
    agg_kernel<<<WB, 256>>>(1);
    gemm_score_kernel<<<GB, 256>>>(xbuf, W2, a2, zbuf, NNODES);
    agg_kernel<<<WB, 256>>>(0);

    reduce_kernel<<<512, 128>>>();
    mlp_kernel<<<1, 128>>>(M0w, M0b, M1w, M1b, M2w, M2b, out);

    cudaEventDestroy(eFork);
    cudaEventDestroy(eCsr);
    cudaStreamDestroy(s2);
}

// round 16
// speedup vs baseline: 1.1819x; 1.0143x over previous
#include <cuda_runtime.h>
#include <cuda_bf16.h>
#include <cstdint>

#define NNODES 50000
#define NEDGES 800000
#define DIM 128
#define SCAN_BLOCKS ((NNODES + 255) / 256)   // 196

// ---------------- scratch (static __device__, no allocs) ----------------
__device__ float g_z[NNODES * DIM];
__device__ float g_x[NNODES * DIM];
__device__ float g_ssrc[NNODES];
__device__ float g_sdst[NNODES];
__device__ int   g_deg[NNODES];
__device__ int   g_off[NNODES + 1];
__device__ int   g_cur[NNODES];
__device__ int   g_csr_src[NEDGES];
__device__ int   g_bsum[SCAN_BLOCKS];
__device__ int   g_bbase[SCAN_BLOCKS + 1];
__device__ float g_hg[DIM];

// ---------------- CSR build (ILP-4 atomics) ----------------
__global__ void hist_kernel(const int* __restrict__ dst) {
    int q = blockIdx.x * blockDim.x + threadIdx.x;
    if (q * 4 < NEDGES) {
        int4 d4 = ((const int4*)dst)[q];
        atomicAdd(&g_deg[d4.x], 1);
        atomicAdd(&g_deg[d4.y], 1);
        atomicAdd(&g_deg[d4.z], 1);
        atomicAdd(&g_deg[d4.w], 1);
    }
}

__global__ void scan1_kernel() {
    __shared__ int sh[256];
    int i = blockIdx.x * 256 + threadIdx.x;
    int v = (i < NNODES) ? g_deg[i] : 0;
    sh[threadIdx.x] = v;
    __syncthreads();
    for (int o = 128; o > 0; o >>= 1) {
        if (threadIdx.x < o) sh[threadIdx.x] += sh[threadIdx.x + o];
        __syncthreads();
    }
    if (threadIdx.x == 0) g_bsum[blockIdx.x] = sh[0];
}

__global__ void scan2_kernel() {
    __shared__ int sh[256];
    int t = threadIdx.x;
    sh[t] = (t < SCAN_BLOCKS) ? g_bsum[t] : 0;
    __syncthreads();
    for (int o = 1; o < 256; o <<= 1) {
        int v = (t >= o) ? sh[t - o] : 0;
        __syncthreads();
        sh[t] += v;
        __syncthreads();
    }
    if (t < SCAN_BLOCKS) g_bbase[t] = (t == 0) ? 0 : sh[t - 1];
    if (t == 255) g_off[NNODES] = sh[SCAN_BLOCKS - 1];
}

__global__ void scan3_kernel() {
    __shared__ int sh[256];
    int t = threadIdx.x;
    int i = blockIdx.x * 256 + t;
    int v = (i < NNODES) ? g_deg[i] : 0;
    sh[t] = v;
    __syncthreads();
    for (int o = 1; o < 256; o <<= 1) {
        int u = (t >= o) ? sh[t - o] : 0;
        __syncthreads();
        sh[t] += u;
        __syncthreads();
    }
    if (i < NNODES) {
        int excl = g_bbase[blockIdx.x] + sh[t] - v;
        g_off[i] = excl;
        g_cur[i] = excl;
    }
}

__global__ void scatter_kernel(const int* __restrict__ src, const int* __restrict__ dst) {
    int q = blockIdx.x * blockDim.x + threadIdx.x;
    if (q * 4 < NEDGES) {
        int4 d4 = ((const int4*)dst)[q];
        int4 s4 = ((const int4*)src)[q];
        int p0 = atomicAdd(&g_cur[d4.x], 1);
        int p1 = atomicAdd(&g_cur[d4.y], 1);
        int p2 = atomicAdd(&g_cur[d4.z], 1);
        int p3 = atomicAdd(&g_cur[d4.w], 1);
        g_csr_src[p0] = s4.x;
        g_csr_src[p1] = s4.y;
        g_csr_src[p2] = s4.z;
        g_csr_src[p3] = s4.w;
    }
}

// ---------------- TF32 tensor-core GEMM + fused attention scores ----------------
// 256 threads = 8 warps. NEW warp tile: 32 rows x 64 cols (wr 0..3, wc 0..1).
// Fragment loads per warp per kk: 8 A + 16 B = 24 LDS (vs 36 for 16x128 tile).
#define BM 128
#define BK 32
#define ASTRIDE 40
#define BSTRIDE 136

__device__ __forceinline__ uint32_t f2tf32(float f) {
    uint32_t u;
    asm("cvt.rna.tf32.f32 %0, %1;" : "=r"(u) : "f"(f));
    return u;
}

__device__ __forceinline__ void mma_tf32(float* d, uint32_t a0, uint32_t a1, uint32_t a2,
                                         uint32_t a3, uint32_t b0, uint32_t b1) {
    asm volatile(
        "mma.sync.aligned.m16n8k8.row.col.f32.tf32.tf32.f32 "
        "{%0,%1,%2,%3}, {%4,%5,%6,%7}, {%8,%9}, {%0,%1,%2,%3};\n"
        : "+f"(d[0]), "+f"(d[1]), "+f"(d[2]), "+f"(d[3])
        : "r"(a0), "r"(a1), "r"(a2), "r"(a3), "r"(b0), "r"(b1));
}

__global__ void __launch_bounds__(256) gemm_score_kernel(const float* __restrict__ A,
                                                         const float* __restrict__ W,
                                                         const float* __restrict__ att,
                                                         float* __restrict__ Z, int M) {
    __shared__ uint32_t As[BM * ASTRIDE];
    __shared__ uint32_t Bs[BK * BSTRIDE];
    __shared__ float sS1[2][BM];
    __shared__ float sS2[2][BM];
    const int tid = threadIdx.x;
    const int warp = tid >> 5;
    const int lane = tid & 31;
    const int gid = lane >> 2;   // 0..7
    const int tig = lane & 3;    // 0..3
    const int wr = warp >> 1;    // 0..3 row group (32 rows each)
    const int wc = warp & 1;     // 0..1 column half (64 cols each)
    const int brow = blockIdx.x * BM;

    const int ar[4] = {(tid + 0) >> 3, (tid + 256) >> 3, (tid + 512) >> 3, (tid + 768) >> 3};
    const int ac = (tid & 7) * 4;
    const int br[4] = {(tid + 0) >> 5, (tid + 256) >> 5, (tid + 512) >> 5, (tid + 768) >> 5};
    const int bc = (tid & 31) * 4;

    // acc[t][nt][4]: t = row-subtile (0: rows wr*32..+16, 1: +16..+32), nt = 0..7 col tile
    float acc[2][8][4];
#pragma unroll
    for (int t = 0; t < 2; t++)
#pragma unroll
        for (int i = 0; i < 8; i++)
#pragma unroll
            for (int j = 0; j < 4; j++) acc[t][i][j] = 0.f;

    float4 pa[4], pb[4];
#pragma unroll
    for (int i = 0; i < 4; i++) {
        pa[i] = make_float4(0.f, 0.f, 0.f, 0.f);
        if (brow + ar[i] < M) pa[i] = *(const float4*)&A[(brow + ar[i]) * 128 + 0 + ac];
        pb[i] = *(const float4*)&W[br[i] * 128 + bc];
    }

#pragma unroll
    for (int t = 0; t < 4; t++) {
#pragma unroll
        for (int i = 0; i < 4; i++) {
            uint32_t* p = &As[ar[i] * ASTRIDE + ac];
            p[0] = f2tf32(pa[i].x); p[1] = f2tf32(pa[i].y);
            p[2] = f2tf32(pa[i].z); p[3] = f2tf32(pa[i].w);
            uint32_t* q = &Bs[br[i] * BSTRIDE + bc];
            q[0] = f2tf32(pb[i].x); q[1] = f2tf32(pb[i].y);
            q[2] = f2tf32(pb[i].z); q[3] = f2tf32(pb[i].w);
        }
        __syncthreads();
        if (t < 3) {
            int k0 = (t + 1) * BK;
#pragma unroll
            for (int i = 0; i < 4; i++) {
                pa[i] = make_float4(0.f, 0.f, 0.f, 0.f);
                if (brow + ar[i] < M) pa[i] = *(const float4*)&A[(brow + ar[i]) * 128 + k0 + ac];
                pb[i] = *(const float4*)&W[(k0 + br[i]) * 128 + bc];
            }
        }
#pragma unroll
        for (int kk = 0; kk < 4; kk++) {
            const int wrow = wr * 32;
            const int kpos = kk * 8 + tig;
            // A fragments: rows wrow+gid, +8, +16, +24
            uint32_t a00 = As[(wrow + gid) * ASTRIDE + kpos];
            uint32_t a01 = As[(wrow + gid + 8) * ASTRIDE + kpos];
            uint32_t a02 = As[(wrow + gid) * ASTRIDE + kpos + 4];
            uint32_t a03 = As[(wrow + gid + 8) * ASTRIDE + kpos + 4];
            uint32_t a10 = As[(wrow + gid + 16) * ASTRIDE + kpos];
            uint32_t a11 = As[(wrow + gid + 24) * ASTRIDE + kpos];
            uint32_t a12 = As[(wrow + gid + 16) * ASTRIDE + kpos + 4];
            uint32_t a13 = As[(wrow + gid + 24) * ASTRIDE + kpos + 4];
#pragma unroll
            for (int nt = 0; nt < 8; nt++) {
                const int n = wc * 64 + nt * 8 + gid;
                uint32_t b0 = Bs[kpos * BSTRIDE + n];
                uint32_t b1 = Bs[(kpos + 4) * BSTRIDE + n];
                mma_tf32(acc[0][nt], a00, a01, a02, a03, b0, b1);
                mma_tf32(acc[1][nt], a10, a11, a12, a13, b0, b1);
            }
        }
        __syncthreads();
    }

    // epilogue: Z stores + partial scores per column half -> smem combine
    float s1[4] = {0.f, 0.f, 0.f, 0.f};   // rows wr*32 + gid, +8, +16, +24
    float s2[4] = {0.f, 0.f, 0.f, 0.f};
#pragma unroll
    for (int t = 0; t < 2; t++) {
        const int ra = brow + wr * 32 + t * 16 + gid;
        const int rb = ra + 8;
#pragma unroll
        for (int nt = 0; nt < 8; nt++) {
            int col = wc * 64 + nt * 8 + tig * 2;
            float al0 = __ldg(&att[col]);
            float al1 = __ldg(&att[col + 1]);
            float ah0 = __ldg(&att[128 + col]);
            float ah1 = __ldg(&att[128 + col + 1]);
            if (ra < M) *(float2*)&Z[ra * 128 + col] = make_float2(acc[t][nt][0], acc[t][nt][1]);
            if (rb < M) *(float2*)&Z[rb * 128 + col] = make_float2(acc[t][nt][2], acc[t][nt][3]);
            s1[t * 2 + 0] += acc[t][nt][0] * al0 + acc[t][nt][1] * al1;
            s2[t * 2 + 0] += acc[t][nt][0] * ah0 + acc[t][nt][1] * ah1;
            s1[t * 2 + 1] += acc[t][nt][2] * al0 + acc[t][nt][3] * al1;
            s2[t * 2 + 1] += acc[t][nt][2] * ah0 + acc[t][nt][3] * ah1;
        }
    }
#pragma unroll
    for (int o = 1; o <= 2; o <<= 1) {
#pragma unroll
        for (int i = 0; i < 4; i++) {
            s1[i] += __shfl_xor_sync(0xffffffffu, s1[i], o);
            s2[i] += __shfl_xor_sync(0xffffffffu, s2[i], o);
        }
    }
    if (tig == 0) {
        // rows: wr*32 + gid + {0, 8, 16, 24} correspond to s indices {0,1,2,3}*... 
        // s index order: [0]=gid, [1]=gid+8 (t=0); [2]=gid+16, [3]=gid+24 (t=1)
        sS1[wc][wr * 32 + gid] = s1[0];
        sS2[wc][wr * 32 + gid] = s2[0];
        sS1[wc][wr * 32 + gid + 8] = s1[1];
        sS2[wc][wr * 32 + gid + 8] = s2[1];
        sS1[wc][wr * 32 + gid + 16] = s1[2];
        sS2[wc][wr * 32 + gid + 16] = s2[2];
        sS1[wc][wr * 32 + gid + 24] = s1[3];
        sS2[wc][wr * 32 + gid + 24] = s2[3];
    }
    __syncthreads();
    if (tid < BM) {
        int r = brow + tid;
        if (r < M) {
            g_ssrc[r] = sS1[0][tid] + sS1[1][tid];
            g_sdst[r] = sS2[0][tid] + sS2[1][tid];
        }
    }
}

// ---------------- fused softmax + aggregation (one warp per dst node) --------
// deg<=32: ILP-4 batched z-row gathers (empirical sweet spot).
__global__ void agg_kernel(int do_elu) {
    int gw = (blockIdx.x * blockDim.x + threadIdx.x) >> 5;
    int lane = threadIdx.x & 31;
    if (gw >= NNODES) return;
    const int beg = g_off[gw];
    const int end = g_off[gw + 1];
    const int deg = end - beg;
    const float4* zrows = (const float4*)g_z;

    float4 o4 = make_float4(0.f, 0.f, 0.f, 0.f);
    if (deg > 0 && deg <= 32) {
        int sidx = 0;
        float w = 0.f;
        if (lane < deg) {
            sidx = __ldg(&g_csr_src[beg + lane]);
            float e = __ldg(&g_ssrc[sidx]) + g_sdst[gw];
            e = (e > 0.f) ? e : 0.01f * e;
            w = __expf(e);
        }
        float d = w;
#pragma unroll
        for (int o = 16; o > 0; o >>= 1) d += __shfl_xor_sync(0xffffffffu, d, o);

        float4 acc0 = make_float4(0.f, 0.f, 0.f, 0.f);
        float4 acc1 = make_float4(0.f, 0.f, 0.f, 0.f);
        float4 acc2 = make_float4(0.f, 0.f, 0.f, 0.f);
        float4 acc3 = make_float4(0.f, 0.f, 0.f, 0.f);
        int j = 0;
        for (; j + 4 <= deg; j += 4) {
            int s0 = __shfl_sync(0xffffffffu, sidx, j);
            int s1 = __shfl_sync(0xffffffffu, sidx, j + 1);
            int s2 = __shfl_sync(0xffffffffu, sidx, j + 2);
            int s3 = __shfl_sync(0xffffffffu, sidx, j + 3);
            float w0 = __shfl_sync(0xffffffffu, w, j);
            float w1 = __shfl_sync(0xffffffffu, w, j + 1);
            float w2 = __shfl_sync(0xffffffffu, w, j + 2);
            float w3 = __shfl_sync(0xffffffffu, w, j + 3);
            float4 z0 = __ldg(&zrows[s0 * 32 + lane]);
            float4 z1 = __ldg(&zrows[s1 * 32 + lane]);
            float4 z2 = __ldg(&zrows[s2 * 32 + lane]);
            float4 z3 = __ldg(&zrows[s3 * 32 + lane]);
            acc0.x += w0 * z0.x; acc0.y += w0 * z0.y; acc0.z += w0 * z0.z; acc0.w += w0 * z0.w;
            acc1.x += w1 * z1.x; acc1.y += w1 * z1.y; acc1.z += w1 * z1.z; acc1.w += w1 * z1.w;
            acc2.x += w2 * z2.x; acc2.y += w2 * z2.y; acc2.z += w2 * z2.z; acc2.w += w2 * z2.w;
            acc3.x += w3 * z3.x; acc3.y += w3 * z3.y; acc3.z += w3 * z3.z; acc3.w += w3 * z3.w;
        }
        for (; j < deg; j++) {
            int s0 = __shfl_sync(0xffffffffu, sidx, j);
            float w0 = __shfl_sync(0xffffffffu, w, j);
            float4 z0 = __ldg(&zrows[s0 * 32 + lane]);
            acc0.x += w0 * z0.x; acc0.y += w0 * z0.y; acc0.z += w0 * z0.z; acc0.w += w0 * z0.w;
        }
        float inv = 1.f / d;
        o4.x = (acc0.x + acc1.x + acc2.x + acc3.x) * inv;
        o4.y = (acc0.y + acc1.y + acc2.y + acc3.y) * inv;
        o4.z = (acc0.z + acc1.z + acc2.z + acc3.z) * inv;
        o4.w = (acc0.w + acc1.w + acc2.w + acc3.w) * inv;
    } else if (deg > 32) {
        const float sdv = g_sdst[gw];
        float d = 0.f;
        for (int i = beg + lane; i < end; i += 32) {
            float e = __ldg(&g_ssrc[__ldg(&g_csr_src[i])]) + sdv;
            e = (e > 0.f) ? e : 0.01f * e;
            d += __expf(e);
        }
#pragma unroll
        for (int o = 16; o > 0; o >>= 1) d += __shfl_xor_sync(0xffffffffu, d, o);
        float4 acc = make_float4(0.f, 0.f, 0.f, 0.f);
        for (int i = beg; i < end; i++) {
            int s = __ldg(&g_csr_src[i]);
            float e = __ldg(&g_ssrc[s]) + sdv;
            e = (e > 0.f) ? e : 0.01f * e;
            float wv = __expf(e);
            float4 zr = __ldg(&zrows[s * 32 + lane]);
            acc.x += wv * zr.x; acc.y += wv * zr.y; acc.z += wv * zr.z; acc.w += wv * zr.w;
        }
        float inv = 1.f / d;
        o4.x = acc.x * inv; o4.y = acc.y * inv; o4.z = acc.z * inv; o4.w = acc.w * inv;
    }
    if (do_elu) {
        o4.x = (o4.x > 0.f) ? o4.x : (__expf(o4.x) - 1.f);
        o4.y = (o4.y > 0.f) ? o4.y : (__expf(o4.y) - 1.f);
        o4.z = (o4.z > 0.f) ? o4.z : (__expf(o4.z) - 1.f);
        o4.w = (o4.w > 0.f) ? o4.w : (__expf(o4.w) - 1.f);
    }
    ((float4*)g_x)[gw * 32 + lane] = o4;
}

// ---------------- mean readout ----------------
__global__ void reduce_kernel() {
    int c = threadIdx.x;
    float s = 0.f;
    for (int r = blockIdx.x; r < NNODES; r += gridDim.x) s += g_x[r * 128 + c];
    atomicAdd(&g_hg[c], s);
}

// ---------------- MLP readout: 128 -> 64 -> 32 -> 3 ----------------
__global__ void mlp_kernel(const float* __restrict__ M0w, const float* __restrict__ M0b,
                           const float* __restrict__ M1w, const float* __restrict__ M1b,
                           const float* __restrict__ M2w, const float* __restrict__ M2b,
                           float* __restrict__ out) {
    __shared__ float h0[128], h1[64], h2[32];
    int t = threadIdx.x;
    h0[t] = g_hg[t] * (1.0f / NNODES);
    __syncthreads();
    if (t < 64) {
        float s = M0b[t];
        for (int k = 0; k < 128; k++) s += h0[k] * M0w[k * 64 + t];
        h1[t] = fmaxf(s, 0.f);
    }
    __syncthreads();
    if (t < 32) {
        float s = M1b[t];
        for (int k = 0; k < 64; k++) s += h1[k] * M1w[k * 32 + t];
        h2[t] = fmaxf(s, 0.f);
    }
    __syncthreads();
    if (t < 3) {
        float s = M2b[t];
        for (int k = 0; k < 32; k++) s += h2[k] * M2w[k * 3 + t];
        out[t] = s;
    }
}

// ---------------- launch: CSR forked onto side stream (R5 structure) --------
extern "C" void kernel_launch(void* const* d_in, const int* in_sizes, int n_in,
                              void* d_out, int out_size) {
    const float* h   = (const float*)d_in[0];
    const int*   src = (const int*)d_in[1];
    const int*   dst = (const int*)d_in[2];
    const float* W0  = (const float*)d_in[3];
    const float* a0  = (const float*)d_in[4];
    const float* W1  = (const float*)d_in[5];
    const float* a1  = (const float*)d_in[6];
    const float* W2  = (const float*)d_in[7];
    const float* a2  = (const float*)d_in[8];
    const float* M0w = (const float*)d_in[9];
    const float* M0b = (const float*)d_in[10];
    const float* M1w = (const float*)d_in[11];
    const float* M1b = (const float*)d_in[12];
    const float* M2w = (const float*)d_in[13];
    const float* M2b = (const float*)d_in[14];
    float* out = (float*)d_out;

    float* zbuf;
    float* xbuf;
    void* degp;
    void* hgp;
    cudaGetSymbolAddress((void**)&zbuf, g_z);
    cudaGetSymbolAddress((void**)&xbuf, g_x);
    cudaGetSymbolAddress(&degp, g_deg);
    cudaGetSymbolAddress(&hgp, g_hg);

    const int QB = (NEDGES / 4 + 255) / 256;
    const int WB = (NNODES * 32 + 255) / 256;
    const int GB = (NNODES + BM - 1) / BM;

    cudaStream_t s2;
    cudaStreamCreateWithFlags(&s2, cudaStreamNonBlocking);
    cudaEvent_t eFork, eCsr;
    cudaEventCreateWithFlags(&eFork, cudaEventDisableTiming);
    cudaEventCreateWithFlags(&eCsr, cudaEventDisableTiming);

    cudaEventRecord(eFork, 0);
    cudaStreamWaitEvent(s2, eFork, 0);

    // CSR branch (side stream)
    cudaMemsetAsync(degp, 0, NNODES * sizeof(int), s2);
    hist_kernel<<<QB, 256, 0, s2>>>(dst);
    scan1_kernel<<<SCAN_BLOCKS, 256, 0, s2>>>();
    scan2_kernel<<<1, 256, 0, s2>>>();
    scan3_kernel<<<SCAN_BLOCKS, 256, 0, s2>>>();
    scatter_kernel<<<QB, 256, 0, s2>>>(src, dst);
    cudaEventRecord(eCsr, s2);

    // main branch
    cudaMemsetAsync(hgp, 0, DIM * sizeof(float));
    gemm_score_kernel<<<GB, 256>>>(h, W0, a0, zbuf, NNODES);
    cudaStreamWaitEvent(0, eCsr, 0);
    agg_kernel<<<WB, 256>>>(1);
    gemm_score_kernel<<<GB, 256>>>(xbuf, W1, a1, zbuf, NNODES);
    agg_kernel<<<WB, 256>>>(1);
    gemm_score_kernel<<<GB, 256>>>(xbuf, W2, a2, zbuf, NNODES);
    agg_kernel<<<WB, 256>>>(0);

    reduce_kernel<<<512, 128>>>();
    mlp_kernel<<<1, 128>>>(M0w, M0b, M1w, M1b, M2w, M2b, out);

    cudaEventDestroy(eFork);
    cudaEventDestroy(eCsr);
    cudaStreamDestroy(s2);
}